// round 11
// baseline (speedup 1.0000x reference)
#include <cuda_runtime.h>

// out[i] = in[i,1] + w*(in[i,0]-in[i,1]).  N = 16777216, pure streaming.
// Champion shape (R10: kernel 26.27us, bench 31.2us, DRAM 78.5%):
// 4 outputs/thread, two adjacent __ldg LDG.128, block 128 x 32768.
// Single delta: store __stcs -> __stwt (write-through; skip L2 allocation for
// the 64MiB write stream, leaving the full LTS to the read stream).

__global__ __launch_bounds__(128)
void skip_kernel(const float4* __restrict__ in,
                 const float* __restrict__ w_ptr,
                 float4* __restrict__ out)
{
    const unsigned i = blockIdx.x * blockDim.x + threadIdx.x;
    const float w = __ldg(w_ptr);

    float4 a = __ldg(&in[2u * i]);
    float4 b = __ldg(&in[2u * i + 1u]);

    float4 o;
    o.x = fmaf(w, a.x - a.y, a.y);
    o.y = fmaf(w, a.z - a.w, a.w);
    o.z = fmaf(w, b.x - b.y, b.y);
    o.w = fmaf(w, b.z - b.w, b.w);

    __stwt(&out[i], o);
}

extern "C" void kernel_launch(void* const* d_in, const int* in_sizes, int n_in,
                              void* d_out, int out_size)
{
    const float* input  = (const float*)d_in[0];   // [N,2]
    const float* weight = (const float*)d_in[1];   // [1,1]
    float*       out    = (float*)d_out;           // [N,1]

    const int n = in_sizes[0] / 2;     // 16777216 outputs
    const int n4 = n / 4;              // 4 outputs per thread, exact
    const int threads = 128;
    const int blocks = n4 / threads;   // 32768

    skip_kernel<<<blocks, threads>>>((const float4*)input, weight, (float4*)out);
}

// round 12
// speedup vs baseline: 1.0523x; 1.0523x over previous
#include <cuda_runtime.h>

// FINAL — converged champion (R10 config).
// out[i] = in[i,1] + w*(in[i,0]-in[i,1]).  N = 16777216, pure streaming,
// 12 B/elem traffic. Measured: kernel 26.27us, HBM 6.22 TB/s (77.8% of spec),
// which matches the sm_103a path-independent LTS/DRAM effective ceiling.
// Shape: 4 outputs/thread, two adjacent default-cached LDG.128,
// one STG.128 evict-first (__stcs, worth -0.8us), block 128 x 32768.
// All alternatives isolated and rejected: 8/thread (L1tex queue contention),
// .cs loads (-bw), LDG.256 (neutral), evict_last (no cross-replay residency),
// __constant__ w (neutral), __stwt (neutral), block 256/512 (equal/worse).

__global__ __launch_bounds__(128)
void skip_kernel(const float4* __restrict__ in,
                 const float* __restrict__ w_ptr,
                 float4* __restrict__ out)
{
    const unsigned i = blockIdx.x * blockDim.x + threadIdx.x;
    const float w = __ldg(w_ptr);

    float4 a = __ldg(&in[2u * i]);
    float4 b = __ldg(&in[2u * i + 1u]);

    float4 o;
    o.x = fmaf(w, a.x - a.y, a.y);
    o.y = fmaf(w, a.z - a.w, a.w);
    o.z = fmaf(w, b.x - b.y, b.y);
    o.w = fmaf(w, b.z - b.w, b.w);

    __stcs(&out[i], o);
}

extern "C" void kernel_launch(void* const* d_in, const int* in_sizes, int n_in,
                              void* d_out, int out_size)
{
    const float* input  = (const float*)d_in[0];   // [N,2]
    const float* weight = (const float*)d_in[1];   // [1,1]
    float*       out    = (float*)d_out;           // [N,1]

    const int n = in_sizes[0] / 2;     // 16777216 outputs
    const int n4 = n / 4;              // 4 outputs per thread, exact
    const int threads = 128;
    const int blocks = n4 / threads;   // 32768

    skip_kernel<<<blocks, threads>>>((const float4*)input, weight, (float4*)out);
}